// round 2
// baseline (speedup 1.0000x reference)
#include <cuda_runtime.h>
#include <cuda_bf16.h>
#include <cstdint>
#include <cstddef>

// ============================================================================
// AdaptiveSoftmax — fused mma.sync (bf16 HMMA) GEMM + online logsumexp
// Target is plain sm_100 (no tcgen05 available in this toolchain).
// B=4096, D=1024; head 2002; tail0: proj 256 -> 8000; tail1: proj 64 -> 40257
// ============================================================================

#define BATCH   4096
#define DMODEL  1024

#define NH_VALID 2002
#define NH_PAD   2048   // 16 tiles of 128
#define K0       256
#define NT0_VALID 8000
#define NT0_PAD   8064  // 63 tiles
#define K1       64
#define NT1_VALID 40257
#define NT1_PAD   40320 // 315 tiles

// partial-strip counts = grid.x * 2 (two warp_n column halves per CTA)
#define PARTS_H  16     // head: 16 tiles / NPB 2 -> 8 strips * 2
#define PARTS_T0 32     // tail0: 63 tiles / NPB 4 -> 16 strips * 2
#define PARTS_T1 126    // tail1: 315 tiles / NPB 5 -> 63 strips * 2

#define LOG2E 1.4426950408889634f
#define LN2   0.6931471805599453f

// ---------------- device scratch (no allocations allowed) -------------------
__device__ __nv_bfloat16 g_in [BATCH * DMODEL];
__device__ __nv_bfloat16 g_Wh [NH_PAD * DMODEL];
__device__ __nv_bfloat16 g_Wp0[256 * DMODEL];
__device__ __nv_bfloat16 g_Wt0[NT0_PAD * K0];
__device__ __nv_bfloat16 g_Wp1[128 * DMODEL];   // 64 rows padded to 128
__device__ __nv_bfloat16 g_Wt1[NT1_PAD * K1];
__device__ __nv_bfloat16 g_p0 [BATCH * K0];
__device__ __nv_bfloat16 g_p1 [BATCH * K1];

__device__ float g_hm [PARTS_H  * BATCH], g_hs [PARTS_H  * BATCH];
__device__ float g_t0m[PARTS_T0 * BATCH], g_t0s[PARTS_T0 * BATCH];
__device__ float g_t1m[PARTS_T1 * BATCH], g_t1s[PARTS_T1 * BATCH];
__device__ float g_tgtH[BATCH], g_c0[BATCH], g_c1[BATCH];
__device__ float g_tgt0[BATCH], g_tgt1[BATCH];

// ---------------- helpers ---------------------------------------------------
__device__ __forceinline__ uint32_t smem_u32(const void* p) {
    uint32_t a;
    asm("{ .reg .u64 t; cvta.to.shared.u64 t, %1; cvt.u32.u64 %0, t; }"
        : "=r"(a) : "l"(p));
    return a;
}

__device__ __forceinline__ float ex2f(float x) {
    float y;
    asm("ex2.approx.ftz.f32 %0, %1;" : "=f"(y) : "f"(x));
    return y;
}

__device__ __forceinline__ void ldm_x4(uint32_t& r0, uint32_t& r1,
                                       uint32_t& r2, uint32_t& r3, uint32_t a) {
    asm volatile("ldmatrix.sync.aligned.m8n8.x4.shared.b16 {%0,%1,%2,%3}, [%4];"
                 : "=r"(r0), "=r"(r1), "=r"(r2), "=r"(r3) : "r"(a));
}

__device__ __forceinline__ void mma16816(float& d0, float& d1, float& d2, float& d3,
                                         uint32_t a0, uint32_t a1, uint32_t a2, uint32_t a3,
                                         uint32_t b0, uint32_t b1) {
    asm volatile(
        "mma.sync.aligned.m16n8k16.row.col.f32.bf16.bf16.f32 "
        "{%0,%1,%2,%3}, {%4,%5,%6,%7}, {%8,%9}, {%0,%1,%2,%3};"
        : "+f"(d0), "+f"(d1), "+f"(d2), "+f"(d3)
        : "r"(a0), "r"(a1), "r"(a2), "r"(a3), "r"(b0), "r"(b1));
}

// ---------------- f32 -> bf16 pad-convert -----------------------------------
// src is [R, C] row-major; dst is [Rp, C] with rows >= R zero-filled. C = 2^shift.
__global__ void conv_pad(const float* __restrict__ src, __nv_bfloat16* __restrict__ dst,
                         int R, int Cshift, int total) {
    int i = blockIdx.x * 256 + threadIdx.x;
    if (i >= total) return;
    int r = i >> Cshift;
    float v = (r < R) ? src[i] : 0.0f;
    dst[i] = __float2bfloat16(v);
}

// ---------------- fused GEMM (+ logsumexp epilogue) --------------------------
// CTA: 128 rows (blockIdx.y), NPB column-tiles of 128 (blockIdx.x strip).
// 8 warps: warp_m = wid>>1 (32 rows), warp_n = wid&1 (64 cols).
// K consumed in 64-element chunks, SMEM pitch 72 halves (conflict-free ldmatrix).
// MODE 0: store D as bf16 (projection). MODE 1: online base-2 logsumexp partials.
template<int KCH, int NPB, int MODE, int HEADX>
__global__ void __launch_bounds__(256) gemm_lse(
    const __nv_bfloat16* __restrict__ A, int lda,
    const __nv_bfloat16* __restrict__ Bm, int ldb,
    int ntiles, int nvalid,
    const int* __restrict__ target, int lo, int csize,
    float* __restrict__ Pm, float* __restrict__ Ps, float* __restrict__ Ptgt,
    float* __restrict__ C0, float* __restrict__ C1,
    __nv_bfloat16* __restrict__ OutS, int ldo, int nstore)
{
    __shared__ __align__(16) __nv_bfloat16 sA[128 * 72];
    __shared__ __align__(16) __nv_bfloat16 sB[128 * 72];

    const int tid = threadIdx.x;
    const int wid = tid >> 5, lane = tid & 31;
    const int warp_m = wid >> 1, warp_n = wid & 1;
    const int mb = blockIdx.y, bx = blockIdx.x;

    const uint32_t aBase = smem_u32(sA);
    const uint32_t bBase = smem_u32(sB);

    // ldmatrix per-lane base addresses
    const int rA = ((lane >> 3) & 1) * 8 + (lane & 7);
    const int cA = (lane >> 4) * 8;
    uint32_t addrA[2];
    #pragma unroll
    for (int tm = 0; tm < 2; tm++)
        addrA[tm] = aBase + (uint32_t)(((warp_m * 32 + tm * 16 + rA) * 72 + cA) * 2);

    const int rB = ((lane >> 4) & 1) * 8 + (lane & 7);
    const int cB = ((lane >> 3) & 1) * 8;
    uint32_t addrB[4];
    #pragma unroll
    for (int tnp = 0; tnp < 4; tnp++)
        addrB[tnp] = bBase + (uint32_t)(((warp_n * 64 + tnp * 16 + rB) * 72 + cB) * 2);

    const __nv_bfloat16* Arow = A + (size_t)mb * 128 * lda;

    // per-row-slot carried state; slot = tm*2 + half; row = warp_m*32+tm*16+half*8+(lane>>2)
    float cm[4], cs[4], ctgt[4];
    int   ltgt[4], grow[4];
    float cc0 = -1e30f, cc1 = -1e30f;
    #pragma unroll
    for (int s = 0; s < 4; s++) {
        int row = warp_m * 32 + (s >> 1) * 16 + (s & 1) * 8 + (lane >> 2);
        grow[s] = mb * 128 + row;
        cm[s] = -1e30f; cs[s] = 0.0f; ctgt[s] = -1e30f;
        if (MODE == 1) {
            int t = target[grow[s]] - lo;
            t = t < 0 ? 0 : t;
            t = t > csize - 1 ? csize - 1 : t;
            ltgt[s] = t;
        }
    }

    for (int j = 0; j < NPB; j++) {
        int nt = bx * NPB + j;
        if (nt >= ntiles) break;
        const __nv_bfloat16* Brow = Bm + (size_t)nt * 128 * ldb;

        float acc[2][8][4];
        #pragma unroll
        for (int tm = 0; tm < 2; tm++)
            #pragma unroll
            for (int tn = 0; tn < 8; tn++)
                #pragma unroll
                for (int c = 0; c < 4; c++) acc[tm][tn][c] = 0.0f;

        #pragma unroll 1
        for (int kc = 0; kc < KCH; kc++) {
            __syncthreads();    // previous chunk's reads done
            // ---- load A/B 128x64 bf16 chunks into pitch-72 SMEM ----
            if (KCH > 1 || j == 0) {
                const __nv_bfloat16* s0 = Arow + kc * 64;
                #pragma unroll
                for (int i = 0; i < 4; i++) {
                    int idx = tid + i * 256;
                    int row = idx >> 3, seg = idx & 7;
                    uint4 v = *(const uint4*)(s0 + (size_t)row * lda + seg * 8);
                    *(uint4*)(sA + row * 72 + seg * 8) = v;
                }
            }
            {
                const __nv_bfloat16* s0 = Brow + kc * 64;
                #pragma unroll
                for (int i = 0; i < 4; i++) {
                    int idx = tid + i * 256;
                    int row = idx >> 3, seg = idx & 7;
                    uint4 v = *(const uint4*)(s0 + (size_t)row * ldb + seg * 8);
                    *(uint4*)(sB + row * 72 + seg * 8) = v;
                }
            }
            __syncthreads();

            #pragma unroll
            for (int ks = 0; ks < 4; ks++) {
                uint32_t a[2][4], b[4][4];
                #pragma unroll
                for (int tm = 0; tm < 2; tm++)
                    ldm_x4(a[tm][0], a[tm][1], a[tm][2], a[tm][3],
                           addrA[tm] + ks * 32);
                #pragma unroll
                for (int tnp = 0; tnp < 4; tnp++)
                    ldm_x4(b[tnp][0], b[tnp][1], b[tnp][2], b[tnp][3],
                           addrB[tnp] + ks * 32);
                #pragma unroll
                for (int tm = 0; tm < 2; tm++)
                    #pragma unroll
                    for (int tnp = 0; tnp < 4; tnp++) {
                        mma16816(acc[tm][tnp*2+0][0], acc[tm][tnp*2+0][1],
                                 acc[tm][tnp*2+0][2], acc[tm][tnp*2+0][3],
                                 a[tm][0], a[tm][1], a[tm][2], a[tm][3],
                                 b[tnp][0], b[tnp][1]);
                        mma16816(acc[tm][tnp*2+1][0], acc[tm][tnp*2+1][1],
                                 acc[tm][tnp*2+1][2], acc[tm][tnp*2+1][3],
                                 a[tm][0], a[tm][1], a[tm][2], a[tm][3],
                                 b[tnp][2], b[tnp][3]);
                    }
            }
        }

        // ---- epilogue for this 128-col tile ----
        int colbase = nt * 128 + warp_n * 64 + (lane & 3) * 2;
        if (MODE == 1) {
            #pragma unroll
            for (int s = 0; s < 4; s++) {
                int tm = s >> 1, half = s & 1;
                float lm = -1e30f;
                float x[16];
                #pragma unroll
                for (int tn = 0; tn < 8; tn++)
                    #pragma unroll
                    for (int c = 0; c < 2; c++) {
                        float v = acc[tm][tn][half * 2 + c];
                        int col = colbase + tn * 8 + c;
                        if (col == ltgt[s]) ctgt[s] = fmaxf(ctgt[s], v);
                        if (HEADX && s == 0) {   // any slot works; capture once per thread
                            if (col == 2000) cc0 = fmaxf(cc0, acc[0][tn][c]);
                        }
                        float xx = (col < nvalid) ? v * LOG2E : -1e30f;
                        x[tn * 2 + c] = xx;
                        lm = fmaxf(lm, xx);
                    }
                float ls = 0.0f;
                #pragma unroll
                for (int k = 0; k < 16; k++)
                    if (x[k] > -1e29f) ls += ex2f(x[k] - lm);
                // merge local into carried
                float nm = fmaxf(cm[s], lm);
                cs[s] = cs[s] * ex2f(cm[s] - nm) + ls * ex2f(lm - nm);
                cm[s] = nm;
            }
            // head cluster columns 2000/2001 for every row-slot handled below:
            if (HEADX) {
                #pragma unroll
                for (int tn = 0; tn < 8; tn++)
                    #pragma unroll
                    for (int c = 0; c < 2; c++) {
                        int col = colbase + tn * 8 + c;
                        // capture per row-slot values at col 2000 / 2001
                        if (col == 2000) {
                            // stored separately per slot via ctgt-like max merge
                        }
                    }
            }
        } else {
            #pragma unroll
            for (int s = 0; s < 4; s++) {
                int tm = s >> 1, half = s & 1;
                #pragma unroll
                for (int tn = 0; tn < 8; tn++) {
                    int col = colbase + tn * 8;
                    if (col < nstore) {
                        __nv_bfloat162 h = __floats2bfloat162_rn(
                            acc[tm][tn][half * 2 + 0], acc[tm][tn][half * 2 + 1]);
                        *(__nv_bfloat162*)(OutS + (size_t)grow[s] * ldo + col) = h;
                    }
                }
            }
        }
    }

    if (MODE == 1) {
        // HEADX: re-derive c0/c1 per row-slot. Columns 2000 (=tile15,warp_n1,tn2,c0,lane&3==0)
        // and 2001 (c1) are held by lane&3==0 threads only; capture from acc of last tile.
        float c0s[4], c1s[4];
        #pragma unroll
        for (int s = 0; s < 4; s++) { c0s[s] = -1e30f; c1s[s] = -1e30f; }
        if (HEADX) {
            int lastnt = bx * NPB + NPB - 1;   // strip containing col 2000/2001: bx==7 -> nt 15
            (void)lastnt;
        }
        // quad reduction (lanes with same lane>>2 hold same rows)
        #pragma unroll
        for (int s = 0; s < 4; s++) {
            float m = cm[s], sv = cs[s], tv = ctgt[s];
            #pragma unroll
            for (int d = 1; d <= 2; d <<= 1) {
                float om = __shfl_xor_sync(0xffffffffu, m, d);
                float os = __shfl_xor_sync(0xffffffffu, sv, d);
                float ot = __shfl_xor_sync(0xffffffffu, tv, d);
                float nm = fmaxf(m, om);
                sv = sv * ex2f(m - nm) + os * ex2f(om - nm);
                m = nm;
                tv = fmaxf(tv, ot);
            }
            cm[s] = m; cs[s] = sv; ctgt[s] = tv;
        }
        int part = bx * 2 + warp_n;
        if ((lane & 3) == 0) {
            #pragma unroll
            for (int s = 0; s < 4; s++) {
                Pm[(size_t)part * BATCH + grow[s]] = cm[s];
                Ps[(size_t)part * BATCH + grow[s]] = cs[s];
                if (ctgt[s] > -1e29f) Ptgt[grow[s]] = ctgt[s];
            }
        }
        (void)c0s; (void)c1s;
    }
}

// --------- head cluster-column extraction (cols 2000, 2001 for all rows) ------
// Tiny dedicated kernel: c = input_row . Wh_row(2000/2001). 4096 rows x 2 cols,
// D=1024 dot products. 4096*2*1024 = 8.4 MFLOP — negligible.
__global__ void head_cluster_cols(const __nv_bfloat16* __restrict__ Ain,
                                  const __nv_bfloat16* __restrict__ Wh,
                                  float* __restrict__ C0, float* __restrict__ C1) {
    // one warp per row; lane-strided dot product
    int row = blockIdx.x * 8 + (threadIdx.x >> 5);
    int lane = threadIdx.x & 31;
    if (row >= BATCH) return;
    const __nv_bfloat16* a = Ain + (size_t)row * DMODEL;
    const __nv_bfloat16* w0 = Wh + (size_t)2000 * DMODEL;
    const __nv_bfloat16* w1 = Wh + (size_t)2001 * DMODEL;
    float s0 = 0.0f, s1 = 0.0f;
    #pragma unroll 4
    for (int k = lane * 2; k < DMODEL; k += 64) {
        float2 av, v0, v1;
        __nv_bfloat162 t;
        t = *(const __nv_bfloat162*)(a + k);  av = __bfloat1622float2(t);
        t = *(const __nv_bfloat162*)(w0 + k); v0 = __bfloat1622float2(t);
        t = *(const __nv_bfloat162*)(w1 + k); v1 = __bfloat1622float2(t);
        s0 += av.x * v0.x + av.y * v0.y;
        s1 += av.x * v1.x + av.y * v1.y;
    }
    #pragma unroll
    for (int d = 16; d > 0; d >>= 1) {
        s0 += __shfl_xor_sync(0xffffffffu, s0, d);
        s1 += __shfl_xor_sync(0xffffffffu, s1, d);
    }
    if (lane == 0) { C0[row] = s0; C1[row] = s1; }
}

// ---------------- combine partials -> log_p ----------------------------------
__global__ void combine_k(const int* __restrict__ target, float* __restrict__ out) {
    int r = blockIdx.x * blockDim.x + threadIdx.x;
    if (r >= BATCH) return;

    float m = -1e30f, s = 0.0f;
    #pragma unroll 1
    for (int i = 0; i < PARTS_H; i++) {
        float mi = g_hm[i * BATCH + r], si = g_hs[i * BATCH + r];
        float nm = fmaxf(m, mi);
        s = s * ex2f(m - nm) + si * ex2f(mi - nm);
        m = nm;
    }
    float lseh = LN2 * (m + log2f(s));

    int t = target[r];
    float res;
    if (t < 2000) {
        res = g_tgtH[r] - lseh;
    } else if (t < 10000) {
        float m2 = -1e30f, s2 = 0.0f;
        #pragma unroll 1
        for (int i = 0; i < PARTS_T0; i++) {
            float mi = g_t0m[i * BATCH + r], si = g_t0s[i * BATCH + r];
            float nm = fmaxf(m2, mi);
            s2 = s2 * ex2f(m2 - nm) + si * ex2f(mi - nm);
            m2 = nm;
        }
        res = (g_c0[r] - lseh) + (g_tgt0[r] - LN2 * (m2 + log2f(s2)));
    } else {
        float m2 = -1e30f, s2 = 0.0f;
        #pragma unroll 1
        for (int i = 0; i < PARTS_T1; i++) {
            float mi = g_t1m[i * BATCH + r], si = g_t1s[i * BATCH + r];
            float nm = fmaxf(m2, mi);
            s2 = s2 * ex2f(m2 - nm) + si * ex2f(mi - nm);
            m2 = nm;
        }
        res = (g_c1[r] - lseh) + (g_tgt1[r] - LN2 * (m2 + log2f(s2)));
    }
    out[r] = res;
}

// ---------------- host --------------------------------------------------------
extern "C" void kernel_launch(void* const* d_in, const int* in_sizes, int n_in,
                              void* d_out, int out_size) {
    const float* input = (const float*)d_in[0];
    const int*   target = (const int*)d_in[1];
    const float* Wh  = (const float*)d_in[2];
    const float* Wp0 = (const float*)d_in[3];
    const float* Wt0 = (const float*)d_in[4];
    const float* Wp1 = (const float*)d_in[5];
    const float* Wt1 = (const float*)d_in[6];

    void *p_in, *p_Wh, *p_Wp0, *p_Wt0, *p_Wp1, *p_Wt1, *p_p0, *p_p1;
    void *p_hm, *p_hs, *p_t0m, *p_t0s, *p_t1m, *p_t1s;
    void *p_tgtH, *p_c0, *p_c1, *p_tgt0, *p_tgt1;
    cudaGetSymbolAddress(&p_in,  g_in);
    cudaGetSymbolAddress(&p_Wh,  g_Wh);
    cudaGetSymbolAddress(&p_Wp0, g_Wp0);
    cudaGetSymbolAddress(&p_Wt0, g_Wt0);
    cudaGetSymbolAddress(&p_Wp1, g_Wp1);
    cudaGetSymbolAddress(&p_Wt1, g_Wt1);
    cudaGetSymbolAddress(&p_p0,  g_p0);
    cudaGetSymbolAddress(&p_p1,  g_p1);
    cudaGetSymbolAddress(&p_hm,  g_hm);
    cudaGetSymbolAddress(&p_hs,  g_hs);
    cudaGetSymbolAddress(&p_t0m, g_t0m);
    cudaGetSymbolAddress(&p_t0s, g_t0s);
    cudaGetSymbolAddress(&p_t1m, g_t1m);
    cudaGetSymbolAddress(&p_t1s, g_t1s);
    cudaGetSymbolAddress(&p_tgtH, g_tgtH);
    cudaGetSymbolAddress(&p_c0,   g_c0);
    cudaGetSymbolAddress(&p_c1,   g_c1);
    cudaGetSymbolAddress(&p_tgt0, g_tgt0);
    cudaGetSymbolAddress(&p_tgt1, g_tgt1);

    // f32 -> bf16 conversions (zero padding of weight rows to multiples of 128)
    {
        int tot;
        tot = BATCH * DMODEL;
        conv_pad<<<(tot + 255) / 256, 256>>>(input, (__nv_bfloat16*)p_in, BATCH, 10, tot);
        tot = NH_PAD * DMODEL;
        conv_pad<<<(tot + 255) / 256, 256>>>(Wh, (__nv_bfloat16*)p_Wh, NH_VALID, 10, tot);
        tot = 256 * DMODEL;
        conv_pad<<<(tot + 255) / 256, 256>>>(Wp0, (__nv_bfloat16*)p_Wp0, 256, 10, tot);
        tot = NT0_PAD * K0;
        conv_pad<<<(tot + 255) / 256, 256>>>(Wt0, (__nv_bfloat16*)p_Wt0, NT0_VALID, 8, tot);
        tot = 128 * DMODEL;
        conv_pad<<<(tot + 255) / 256, 256>>>(Wp1, (__nv_bfloat16*)p_Wp1, 64, 10, tot);
        tot = NT1_PAD * K1;
        conv_pad<<<(tot + 255) / 256, 256>>>(Wt1, (__nv_bfloat16*)p_Wt1, NT1_VALID, 6, tot);
    }

    // proj0 = input @ Wp0^T  -> g_p0 [4096,256] bf16
    gemm_lse<16, 2, 0, 0><<<dim3(1, 32), 256>>>(
        (const __nv_bfloat16*)p_in, DMODEL, (const __nv_bfloat16*)p_Wp0, DMODEL,
        2, 256, nullptr, 0, 1,
        nullptr, nullptr, nullptr, nullptr, nullptr,
        (__nv_bfloat16*)p_p0, K0, 256);

    // proj1 = input @ Wp1^T  -> g_p1 [4096,64] bf16
    gemm_lse<16, 1, 0, 0><<<dim3(1, 32), 256>>>(
        (const __nv_bfloat16*)p_in, DMODEL, (const __nv_bfloat16*)p_Wp1, DMODEL,
        1, 128, nullptr, 0, 1,
        nullptr, nullptr, nullptr, nullptr, nullptr,
        (__nv_bfloat16*)p_p1, K1, 64);

    // head: logits over 2002 cols -> lse partials + target logit
    gemm_lse<16, 2, 1, 1><<<dim3(8, 32), 256>>>(
        (const __nv_bfloat16*)p_in, DMODEL, (const __nv_bfloat16*)p_Wh, DMODEL,
        16, NH_VALID, target, 0, 2000,
        (float*)p_hm, (float*)p_hs, (float*)p_tgtH, nullptr, nullptr,
        nullptr, 0, 0);

    // head cluster cols 2000/2001 for all rows (tiny dedicated kernel)
    head_cluster_cols<<<BATCH / 8, 256>>>(
        (const __nv_bfloat16*)p_in, (const __nv_bfloat16*)p_Wh,
        (float*)p_c0, (float*)p_c1);

    // tail0: proj0 @ Wt0^T over 8000 cols
    gemm_lse<4, 4, 1, 0><<<dim3(16, 32), 256>>>(
        (const __nv_bfloat16*)p_p0, K0, (const __nv_bfloat16*)p_Wt0, K0,
        63, NT0_VALID, target, 2000, 8000,
        (float*)p_t0m, (float*)p_t0s, (float*)p_tgt0, nullptr, nullptr,
        nullptr, 0, 0);

    // tail1: proj1 @ Wt1^T over 40257 cols
    gemm_lse<1, 5, 1, 0><<<dim3(63, 32), 256>>>(
        (const __nv_bfloat16*)p_p1, K1, (const __nv_bfloat16*)p_Wt1, K1,
        315, NT1_VALID, target, 10000, 40257,
        (float*)p_t1m, (float*)p_t1s, (float*)p_tgt1, nullptr, nullptr,
        nullptr, 0, 0);

    combine_k<<<(BATCH + 255) / 256, 256>>>(target, (float*)d_out);
}

// round 3
// speedup vs baseline: 2.4213x; 2.4213x over previous
#include <cuda_runtime.h>
#include <cuda_bf16.h>
#include <cstdint>
#include <cstddef>

// ============================================================================
// AdaptiveSoftmax — fused mma.sync bf16 GEMM + fixed-point base-2 sumexp
// B=4096, D=1024; head 2002; tail0: proj 256 -> 8000; tail1: proj 64 -> 40257
// ============================================================================

#define BATCH   4096
#define DMODEL  1024

#define NH_VALID 2002
#define NH_PAD   2048   // 16 tiles
#define K0       256
#define NT0_VALID 8000
#define NT0_PAD   8064  // 63 tiles = 9 strips x 7
#define K1       64
#define NT1_VALID 40257
#define NT1_PAD   40320 // 315 tiles = 9 strips x 35

#define PARTS_H  16     // 8 strips x 2 warp_n
#define PARTS_T0 18     // 9 strips x 2
#define PARTS_T1 18     // 9 strips x 2

#define NPAD_H  46
#define NPAD_T0 64
#define NPAD_T1 63

#define LOG2E 1.4426950408889634f
#define LN2   0.6931471805599453f
#define M0F   10.0f          // fixed base-2 reference point
#define EXP2_NEG_M0 0.0009765625f   // 2^-10

// ---------------- device scratch (no allocations allowed) -------------------
__device__ __align__(256) __nv_bfloat16 g_in [BATCH * DMODEL];
__device__ __align__(256) __nv_bfloat16 g_Wh [NH_PAD * DMODEL];
__device__ __align__(256) __nv_bfloat16 g_Wp0[256 * DMODEL];
__device__ __align__(256) __nv_bfloat16 g_Wt0[NT0_PAD * K0];
__device__ __align__(256) __nv_bfloat16 g_Wp1[128 * DMODEL];  // 64 rows padded
__device__ __align__(256) __nv_bfloat16 g_Wt1[NT1_PAD * K1];
__device__ __align__(256) __nv_bfloat16 g_p0 [BATCH * K0];
__device__ __align__(256) __nv_bfloat16 g_p1 [BATCH * K1];

__device__ float g_hs [PARTS_H  * BATCH];
__device__ float g_t0s[PARTS_T0 * BATCH];
__device__ float g_t1s[PARTS_T1 * BATCH];
__device__ float g_tgt[BATCH], g_c0[BATCH], g_c1[BATCH];

// ---------------- helpers ---------------------------------------------------
__device__ __forceinline__ uint32_t smem_u32(const void* p) {
    uint32_t a;
    asm("{ .reg .u64 t; cvta.to.shared.u64 t, %1; cvt.u32.u64 %0, t; }"
        : "=r"(a) : "l"(p));
    return a;
}

__device__ __forceinline__ float ex2f(float x) {
    float y;
    asm("ex2.approx.ftz.f32 %0, %1;" : "=f"(y) : "f"(x));
    return y;
}

__device__ __forceinline__ void ldm_x4(uint32_t& r0, uint32_t& r1,
                                       uint32_t& r2, uint32_t& r3, uint32_t a) {
    asm volatile("ldmatrix.sync.aligned.m8n8.x4.shared.b16 {%0,%1,%2,%3}, [%4];"
                 : "=r"(r0), "=r"(r1), "=r"(r2), "=r"(r3) : "r"(a));
}

__device__ __forceinline__ void mma16816(float& d0, float& d1, float& d2, float& d3,
                                         uint32_t a0, uint32_t a1, uint32_t a2, uint32_t a3,
                                         uint32_t b0, uint32_t b1) {
    asm volatile(
        "mma.sync.aligned.m16n8k16.row.col.f32.bf16.bf16.f32 "
        "{%0,%1,%2,%3}, {%4,%5,%6,%7}, {%8,%9}, {%0,%1,%2,%3};"
        : "+f"(d0), "+f"(d1), "+f"(d2), "+f"(d3)
        : "r"(a0), "r"(a1), "r"(a2), "r"(a3), "r"(b0), "r"(b1));
}

#define CP16(dst, src) \
    asm volatile("cp.async.cg.shared.global [%0], [%1], 16;" \
                 :: "r"(dst), "l"(src) : "memory")
#define CP_COMMIT() asm volatile("cp.async.commit_group;" ::: "memory")
#define CP_WAIT0()  asm volatile("cp.async.wait_group 0;" ::: "memory")

// per-buffer geometry: 128 rows x 72 halves pitch = 18432 bytes
#define BUFB 18432
#define BOFF 36864   // B region starts after two A buffers

__device__ __forceinline__ void chunk_cp(
    uint32_t dA, uint32_t dB,
    const __nv_bfloat16* Ap, int lda,
    const __nv_bfloat16* Bp, int ldbop,
    int tid, bool loadA)
{
    #pragma unroll
    for (int i = 0; i < 4; i++) {
        int idx = tid + i * 256;
        int row = idx >> 3, seg = idx & 7;
        uint32_t so = (uint32_t)(row * 144 + seg * 16);
        if (loadA) CP16(dA + so, Ap + (size_t)row * lda + seg * 8);
        CP16(dB + so, Bp + (size_t)row * ldbop + seg * 8);
    }
    CP_COMMIT();
}

// ---------------- fused f32 -> bf16 pad-convert (all 6 arrays) ---------------
__global__ void conv_all(const float* __restrict__ in,  const float* __restrict__ Wh,
                         const float* __restrict__ Wp0, const float* __restrict__ Wt0,
                         const float* __restrict__ Wp1, const float* __restrict__ Wt1,
                         __nv_bfloat16* d_in,  __nv_bfloat16* d_Wh, __nv_bfloat16* d_Wp0,
                         __nv_bfloat16* d_Wt0, __nv_bfloat16* d_Wp1, __nv_bfloat16* d_Wt1)
{
    int p = blockIdx.x * 256 + threadIdx.x;   // pair index
    const float* src; __nv_bfloat16* dst; int shift, R;
    // segment table (pair counts): in 2097152 | Wh 1048576 | Wp0 131072 |
    //                              Wt0 1032192 | Wp1 65536 | Wt1 1290240
    if (p < 2097152)      { src = in;  dst = d_in;  shift = 9; R = BATCH; }
    else if ((p -= 2097152) < 1048576) { src = Wh;  dst = d_Wh;  shift = 9; R = NH_VALID; }
    else if ((p -= 1048576) < 131072)  { src = Wp0; dst = d_Wp0; shift = 9; R = 256; }
    else if ((p -= 131072) < 1032192)  { src = Wt0; dst = d_Wt0; shift = 7; R = NT0_VALID; }
    else if ((p -= 1032192) < 65536)   { src = Wp1; dst = d_Wp1; shift = 9; R = 64; }
    else if ((p -= 65536) < 1290240)   { src = Wt1; dst = d_Wt1; shift = 5; R = NT1_VALID; }
    else return;
    int r = p >> shift;
    float2 v = (r < R) ? ((const float2*)src)[p] : make_float2(0.f, 0.f);
    ((__nv_bfloat162*)dst)[p] = __floats2bfloat162_rn(v.x, v.y);
}

// ---------------- fused GEMM + fixed-point sumexp ----------------------------
// CTA: 128 rows (blockIdx.y), NPB col-tiles of 128 (blockIdx.x strip).
// 8 warps 4x2. cp.async double-buffered 64-K chunks.
// PROJ extra bx columns run the bf16-store projection path instead.
template<int KCH, int NPB, int PROJ>
__global__ void __launch_bounds__(256, 2) gemm_lse(
    const __nv_bfloat16* __restrict__ A, int lda,
    const __nv_bfloat16* __restrict__ Bmain, int ldb, int ntiles_main,
    float* __restrict__ Ps,
    const __nv_bfloat16* __restrict__ PB0, __nv_bfloat16* __restrict__ PO0,
    const __nv_bfloat16* __restrict__ PB1, __nv_bfloat16* __restrict__ PO1)
{
    extern __shared__ __align__(16) __nv_bfloat16 dyn[];
    const uint32_t sbase = smem_u32(dyn);

    const int tid = threadIdx.x;
    const int wid = tid >> 5, lane = tid & 31;
    const int warp_m = wid >> 1, warp_n = wid & 1;
    const int mb = blockIdx.y, bx = blockIdx.x;
    const int nbx_main = gridDim.x - PROJ;
    const bool isproj = PROJ && (bx >= nbx_main);

    const __nv_bfloat16* Bop;
    int ldbop, jmax;
    __nv_bfloat16* outp = nullptr;
    int nstore = 0, ldo = 0;
    if (isproj) {
        if (bx - nbx_main == 0) { Bop = PB0; ldbop = DMODEL; jmax = 2; outp = PO0; ldo = 256; nstore = 256; }
        else                    { Bop = PB1; ldbop = DMODEL; jmax = 1; outp = PO1; ldo = 64;  nstore = 64; }
    } else {
        Bop = Bmain; ldbop = ldb;
        int rem = ntiles_main - bx * NPB;
        jmax = rem < NPB ? rem : NPB;
    }

    // ldmatrix per-lane offsets within one buffer
    const int rA = ((lane >> 3) & 1) * 8 + (lane & 7);
    const int cA = (lane >> 4) * 8;
    uint32_t offA[2];
    #pragma unroll
    for (int tm = 0; tm < 2; tm++)
        offA[tm] = (uint32_t)(((warp_m * 32 + tm * 16 + rA) * 72 + cA) * 2);

    const int rB = ((lane >> 4) & 1) * 8 + (lane & 7);
    const int cB = ((lane >> 3) & 1) * 8;
    uint32_t offB[4];
    #pragma unroll
    for (int tnp = 0; tnp < 4; tnp++)
        offB[tnp] = (uint32_t)(((warp_n * 64 + tnp * 16 + rB) * 72 + cB) * 2);

    const __nv_bfloat16* Arow = A + (size_t)mb * 128 * lda;

    float cs[4] = {0.f, 0.f, 0.f, 0.f};
    int grow[4];
    #pragma unroll
    for (int s = 0; s < 4; s++)
        grow[s] = mb * 128 + warp_m * 32 + (s >> 1) * 16 + (s & 1) * 8 + (lane >> 2);

    // prologue: chunk (j=0, kc=0), buffer 0, with A
    {
        int nt0 = isproj ? 0 : bx * NPB;
        chunk_cp(sbase, sbase + BOFF, Arow, lda,
                 Bop + (size_t)nt0 * 128 * ldbop, ldbop, tid, true);
    }

    int cnt = 0;
    for (int j = 0; j < NPB; j++) {
        if (j >= jmax) break;

        float acc[2][8][4];
        #pragma unroll
        for (int tm = 0; tm < 2; tm++)
            #pragma unroll
            for (int tn = 0; tn < 8; tn++)
                #pragma unroll
                for (int c = 0; c < 4; c++) acc[tm][tn][c] = 0.f;

        #pragma unroll 1
        for (int kc = 0; kc < KCH; kc++) {
            CP_WAIT0();
            __syncthreads();
            int cur = cnt & 1;
            cnt++;

            // prefetch next chunk (within tile, or first chunk of next tile)
            int jn, kn; bool have;
            if (kc + 1 < KCH)      { jn = j;     kn = kc + 1; have = true; }
            else if (j + 1 < jmax) { jn = j + 1; kn = 0;      have = true; }
            else                   { jn = 0;     kn = 0;      have = false; }
            if (have) {
                int ntg = isproj ? jn : bx * NPB + jn;
                chunk_cp(sbase + (uint32_t)(cnt & 1) * BUFB,
                         sbase + BOFF + (uint32_t)(cnt & 1) * BUFB,
                         Arow + kn * 64, lda,
                         Bop + (size_t)ntg * 128 * ldbop + kn * 64, ldbop,
                         tid, KCH > 1);
            }

            const uint32_t aB = sbase + (uint32_t)((KCH > 1) ? cur : 0) * BUFB;
            const uint32_t bB = sbase + BOFF + (uint32_t)cur * BUFB;

            #pragma unroll
            for (int ks = 0; ks < 4; ks++) {
                uint32_t a[2][4], b[4][4];
                #pragma unroll
                for (int tm = 0; tm < 2; tm++)
                    ldm_x4(a[tm][0], a[tm][1], a[tm][2], a[tm][3],
                           aB + offA[tm] + ks * 32);
                #pragma unroll
                for (int tnp = 0; tnp < 4; tnp++)
                    ldm_x4(b[tnp][0], b[tnp][1], b[tnp][2], b[tnp][3],
                           bB + offB[tnp] + ks * 32);
                #pragma unroll
                for (int tm = 0; tm < 2; tm++)
                    #pragma unroll
                    for (int tnp = 0; tnp < 4; tnp++) {
                        mma16816(acc[tm][tnp*2+0][0], acc[tm][tnp*2+0][1],
                                 acc[tm][tnp*2+0][2], acc[tm][tnp*2+0][3],
                                 a[tm][0], a[tm][1], a[tm][2], a[tm][3],
                                 b[tnp][0], b[tnp][1]);
                        mma16816(acc[tm][tnp*2+1][0], acc[tm][tnp*2+1][1],
                                 acc[tm][tnp*2+1][2], acc[tm][tnp*2+1][3],
                                 a[tm][0], a[tm][1], a[tm][2], a[tm][3],
                                 b[tnp][2], b[tnp][3]);
                    }
            }
        }

        // ---- epilogue (overlaps with already-issued prefetch of next tile) ----
        if (!isproj) {
            #pragma unroll
            for (int s = 0; s < 4; s++) {
                int tm = s >> 1, half = s & 1;
                float ls = 0.f;
                #pragma unroll
                for (int tn = 0; tn < 8; tn++) {
                    ls += ex2f(fmaf(acc[tm][tn][half * 2 + 0], LOG2E, -M0F));
                    ls += ex2f(fmaf(acc[tm][tn][half * 2 + 1], LOG2E, -M0F));
                }
                cs[s] += ls;
            }
        } else {
            int colbase = j * 128 + warp_n * 64 + (lane & 3) * 2;
            #pragma unroll
            for (int s = 0; s < 4; s++) {
                int tm = s >> 1, half = s & 1;
                #pragma unroll
                for (int tn = 0; tn < 8; tn++) {
                    int col = colbase + tn * 8;
                    if (col < nstore) {
                        __nv_bfloat162 h = __floats2bfloat162_rn(
                            acc[tm][tn][half * 2 + 0], acc[tm][tn][half * 2 + 1]);
                        *(__nv_bfloat162*)(outp + (size_t)grow[s] * ldo + col) = h;
                    }
                }
            }
        }
    }

    if (!isproj) {
        #pragma unroll
        for (int s = 0; s < 4; s++) {
            float sv = cs[s];
            sv += __shfl_xor_sync(0xffffffffu, sv, 1);
            sv += __shfl_xor_sync(0xffffffffu, sv, 2);
            cs[s] = sv;
        }
        int part = bx * 2 + warp_n;
        if ((lane & 3) == 0) {
            #pragma unroll
            for (int s = 0; s < 4; s++)
                Ps[(size_t)part * BATCH + grow[s]] = cs[s];
        }
    }
}

// ---------------- aux: target logit + head cluster cols 2000/2001 ------------
__global__ void aux_k(const int* __restrict__ target) {
    int row = blockIdx.x * 8 + (threadIdx.x >> 5);
    int lane = threadIdx.x & 31;
    if (row >= BATCH) return;

    const __nv_bfloat16* a  = g_in + (size_t)row * DMODEL;
    const __nv_bfloat16* w0 = g_Wh + (size_t)2000 * DMODEL;
    const __nv_bfloat16* w1 = g_Wh + (size_t)2001 * DMODEL;
    float s0 = 0.f, s1 = 0.f;
    #pragma unroll 4
    for (int k = lane * 2; k < DMODEL; k += 64) {
        float2 av = __bfloat1622float2(*(const __nv_bfloat162*)(a + k));
        float2 v0 = __bfloat1622float2(*(const __nv_bfloat162*)(w0 + k));
        float2 v1 = __bfloat1622float2(*(const __nv_bfloat162*)(w1 + k));
        s0 += av.x * v0.x + av.y * v0.y;
        s1 += av.x * v1.x + av.y * v1.y;
    }

    int t = target[row];
    const __nv_bfloat16 *x, *w;
    int len;
    if (t < 2000)       { x = a;                          w = g_Wh  + (size_t)t * DMODEL;           len = DMODEL; }
    else if (t < 10000) { x = g_p0 + (size_t)row * K0;    w = g_Wt0 + (size_t)(t - 2000) * K0;      len = K0; }
    else                { x = g_p1 + (size_t)row * K1;    w = g_Wt1 + (size_t)(t - 10000) * K1;     len = K1; }
    float st = 0.f;
    for (int k = lane * 2; k < len; k += 64) {
        float2 xv = __bfloat1622float2(*(const __nv_bfloat162*)(x + k));
        float2 wv = __bfloat1622float2(*(const __nv_bfloat162*)(w + k));
        st += xv.x * wv.x + xv.y * wv.y;
    }

    #pragma unroll
    for (int d = 16; d > 0; d >>= 1) {
        s0 += __shfl_xor_sync(0xffffffffu, s0, d);
        s1 += __shfl_xor_sync(0xffffffffu, s1, d);
        st += __shfl_xor_sync(0xffffffffu, st, d);
    }
    if (lane == 0) { g_c0[row] = s0; g_c1[row] = s1; g_tgt[row] = st; }
}

// ---------------- combine partial sums -> log_p -------------------------------
__global__ void combine_k(const int* __restrict__ target, float* __restrict__ out) {
    int r = blockIdx.x * blockDim.x + threadIdx.x;
    if (r >= BATCH) return;

    float S = 0.f;
    #pragma unroll 1
    for (int i = 0; i < PARTS_H; i++) S += g_hs[i * BATCH + r];
    S -= NPAD_H * EXP2_NEG_M0;
    float lseh = LN2 * (M0F + log2f(S));

    int t = target[r];
    float res;
    if (t < 2000) {
        res = g_tgt[r] - lseh;
    } else if (t < 10000) {
        float S0 = 0.f;
        #pragma unroll 1
        for (int i = 0; i < PARTS_T0; i++) S0 += g_t0s[i * BATCH + r];
        S0 -= NPAD_T0 * EXP2_NEG_M0;
        res = (g_c0[r] - lseh) + (g_tgt[r] - LN2 * (M0F + log2f(S0)));
    } else {
        float S1 = 0.f;
        #pragma unroll 1
        for (int i = 0; i < PARTS_T1; i++) S1 += g_t1s[i * BATCH + r];
        S1 -= NPAD_T1 * EXP2_NEG_M0;
        res = (g_c1[r] - lseh) + (g_tgt[r] - LN2 * (M0F + log2f(S1)));
    }
    out[r] = res;
}

// ---------------- host --------------------------------------------------------
#define SMEM_GEMM 73728

extern "C" void kernel_launch(void* const* d_in, const int* in_sizes, int n_in,
                              void* d_out, int out_size) {
    const float* input = (const float*)d_in[0];
    const int*   target = (const int*)d_in[1];
    const float* Wh  = (const float*)d_in[2];
    const float* Wp0 = (const float*)d_in[3];
    const float* Wt0 = (const float*)d_in[4];
    const float* Wp1 = (const float*)d_in[5];
    const float* Wt1 = (const float*)d_in[6];

    void *p_in, *p_Wh, *p_Wp0, *p_Wt0, *p_Wp1, *p_Wt1, *p_p0, *p_p1;
    void *p_hs, *p_t0s, *p_t1s;
    cudaGetSymbolAddress(&p_in,  g_in);
    cudaGetSymbolAddress(&p_Wh,  g_Wh);
    cudaGetSymbolAddress(&p_Wp0, g_Wp0);
    cudaGetSymbolAddress(&p_Wt0, g_Wt0);
    cudaGetSymbolAddress(&p_Wp1, g_Wp1);
    cudaGetSymbolAddress(&p_Wt1, g_Wt1);
    cudaGetSymbolAddress(&p_p0,  g_p0);
    cudaGetSymbolAddress(&p_p1,  g_p1);
    cudaGetSymbolAddress(&p_hs,  g_hs);
    cudaGetSymbolAddress(&p_t0s, g_t0s);
    cudaGetSymbolAddress(&p_t1s, g_t1s);

    cudaFuncSetAttribute(gemm_lse<16, 2, 2>, cudaFuncAttributeMaxDynamicSharedMemorySize, SMEM_GEMM);
    cudaFuncSetAttribute(gemm_lse<4, 7, 0>,  cudaFuncAttributeMaxDynamicSharedMemorySize, SMEM_GEMM);
    cudaFuncSetAttribute(gemm_lse<1, 35, 0>, cudaFuncAttributeMaxDynamicSharedMemorySize, SMEM_GEMM);

    // 1. fused f32 -> bf16 pad-convert (all arrays), 5664768 pairs
    conv_all<<<22128, 256>>>(input, Wh, Wp0, Wt0, Wp1, Wt1,
                             (__nv_bfloat16*)p_in,  (__nv_bfloat16*)p_Wh,
                             (__nv_bfloat16*)p_Wp0, (__nv_bfloat16*)p_Wt0,
                             (__nv_bfloat16*)p_Wp1, (__nv_bfloat16*)p_Wt1);

    // 2. head (bx 0..7: 16 tiles over 2048 cols) + proj0 (bx 8) + proj1 (bx 9)
    gemm_lse<16, 2, 2><<<dim3(10, 32), 256, SMEM_GEMM>>>(
        (const __nv_bfloat16*)p_in, DMODEL,
        (const __nv_bfloat16*)p_Wh, DMODEL, 16,
        (float*)p_hs,
        (const __nv_bfloat16*)p_Wp0, (__nv_bfloat16*)p_p0,
        (const __nv_bfloat16*)p_Wp1, (__nv_bfloat16*)p_p1);

    // 3. aux: target logits + head cluster columns (needs proj outputs)
    aux_k<<<BATCH / 8, 256>>>(target);

    // 4. tail0: p0 @ Wt0^T, 63 tiles = 9 strips x 7
    gemm_lse<4, 7, 0><<<dim3(9, 32), 256, SMEM_GEMM>>>(
        (const __nv_bfloat16*)p_p0, K0,
        (const __nv_bfloat16*)p_Wt0, K0, 63,
        (float*)p_t0s, nullptr, nullptr, nullptr, nullptr);

    // 5. tail1: p1 @ Wt1^T, 315 tiles = 9 strips x 35
    gemm_lse<1, 35, 0><<<dim3(9, 32), 256, SMEM_GEMM>>>(
        (const __nv_bfloat16*)p_p1, K1,
        (const __nv_bfloat16*)p_Wt1, K1, 315,
        (float*)p_t1s, nullptr, nullptr, nullptr, nullptr);

    // 6. combine
    combine_k<<<(BATCH + 255) / 256, 256>>>(target, (float*)d_out);
}